// round 13
// baseline (speedup 1.0000x reference)
#include <cuda_runtime.h>
#include <cuda_fp16.h>
#include <cstdint>

// Problem constants
#define DD    128
#define MAXN  50000
#define MAXR  8
#define KS    256     // split-K both layers: [hi | lo] . [Whi | Whi]
#define NOUT1 1152    // R*D + D (root)
#define MAXE  600000
#define MAXT  ((MAXN + 127) / 128)
#define MAXB  (MAXT * MAXR)

// ---------------- device scratch ----------------
__device__ __half   g_A1  [(size_t)MAXN * KS];   // split X (fp16)
__device__ __half   g_A2  [(size_t)MAXN * KS];   // split h1 (fp16)
__device__ __half   g_W1T [NOUT1 * KS];          // layer-1 B operand [Nout, K]
__device__ __half   g_W2T [256 * KS];            // layer-2 B operand [root|rel]
__device__ float    g_yroot[(size_t)MAXN * DD];
__device__ float    g_agg  [(size_t)MAXN * DD];
__device__ int      g_cnt [MAXN * MAXR];
__device__ int      g_hist[MAXB];
__device__ int      g_seg [MAXB + 1];
__device__ int      g_cur [MAXB];
__device__ uint32_t g_epk [MAXE];   // dst | (src&127)<<17
__device__ float    g_enorm[MAXE];

__device__ __forceinline__ uint32_t smem_u32(const void* p) {
    uint32_t a;
    asm("{ .reg .u64 t; cvta.to.shared.u64 t, %1; cvt.u32.u64 %0, t; }" : "=r"(a) : "l"(p));
    return a;
}

// ---------------- inline index dtype detection ----------------
__device__ __forceinline__ int is_w64(const int* __restrict__ ei32) {
    return ((ei32[1] | ei32[3] | ei32[5] | ei32[7]) == 0) ? 1 : 0;
}
__device__ __forceinline__ long long getIdx(const void* __restrict__ p, size_t i, int w64) {
    if (w64) return ((const long long*)p)[i];
    return (long long)((const int*)p)[i];
}

// ---------------- 8-wide fp16 split pack ----------------
union Pack8h {
    __half b[8];
    uint4 u;
};
__device__ __forceinline__ void split8h(float4 a, float4 c, uint4& hi, uint4& lo) {
    float f[8] = {a.x, a.y, a.z, a.w, c.x, c.y, c.z, c.w};
    Pack8h H, L;
#pragma unroll
    for (int j = 0; j < 8; j++) {
        __half h = __float2half_rn(f[j]);
        H.b[j] = h;
        L.b[j] = __float2half_rn(f[j] - __half2float(h));
    }
    hi = H.u;
    lo = L.u;
}

// ---------------- branch-A prep: zero agg/d_out | build weights | split X ----------------
__global__ void k_prep(const float* __restrict__ x, const float* __restrict__ basis,
                       const float* __restrict__ comp, const float* __restrict__ root,
                       const float* __restrict__ w_rel, const float* __restrict__ w_root,
                       float* __restrict__ dout, int n, int B_) {
    int id = blockIdx.x * blockDim.x + threadIdx.x;
    const int Z = n * 32;                  // zero range (float4 over N*128)
    const int W = (NOUT1 + 256) * DD;      // weight elements
    if (id < Z) {
        ((float4*)g_agg)[id] = make_float4(0.f, 0.f, 0.f, 0.f);
        ((float4*)dout)[id] = make_float4(0.f, 0.f, 0.f, 0.f);
    } else if (id < Z + W) {
        int idx = id - Z;
        const int nrel = MAXR * DD * DD;       // 131072
        const int n1 = NOUT1 * DD;             // 147456
        if (idx < nrel) {
            int o = idx & 127, c = (idx >> 7) & 127, rr = idx >> 14;
            float w = 0.f;
            for (int b = 0; b < B_; b++)
                w += comp[rr * B_ + b] * basis[((size_t)b * DD + c) * DD + o];
            __half hi = __float2half_rn(w);
            int j = rr * DD + o;
            g_W1T[j * KS + c] = hi;
            g_W1T[j * KS + 128 + c] = hi;
        } else if (idx < n1) {
            int i2 = idx - nrel;
            int o = i2 & 127, c = (i2 >> 7) & 127;
            __half hi = __float2half_rn(root[c * DD + o]);
            int j = MAXR * DD + o;
            g_W1T[j * KS + c] = hi;
            g_W1T[j * KS + 128 + c] = hi;
        } else {
            int t = idx - n1;
            int o = t >> 7, c = t & 127;   // o<128: w_root row o ; o>=128: w_rel row o-128
            float w = (o < DD) ? w_root[o * DD + c] : w_rel[(o - DD) * DD + c];
            __half hi = __float2half_rn(w);
            g_W2T[o * KS + c] = hi;
            g_W2T[o * KS + 128 + c] = hi;
        }
    } else if (id < Z + W + n * 16) {
        int i = id - Z - W;
        int nn = i >> 4, g = i & 15;
        const float4* src = (const float4*)(x + (size_t)nn * DD + g * 8);
        uint4 hi, lo;
        split8h(src[0], src[1], hi, lo);
        __half* base = g_A1 + (size_t)nn * KS + g * 8;
        *(uint4*)(base) = hi;
        *(uint4*)(base + 128) = lo;
    }
}

// ---------------- branch-B zero: cnt + hist (owned by bucketing chain) ----------------
__global__ void k_zero_cnt_hist(int n, int r, int nb) {
    int i = blockIdx.x * blockDim.x + threadIdx.x;
    if (i < (n * r + 3) / 4) ((int4*)g_cnt)[i] = make_int4(0, 0, 0, 0);
    if (i < nb) g_hist[i] = 0;
}

// ---------------- per-(dst,rel) count + per-(srcblk,rel) histogram ----------------
__global__ void k_count_hist(const void* __restrict__ ei, const void* __restrict__ et, int e,
                             int r) {
    int i = blockIdx.x * blockDim.x + threadIdx.x;
    if (i >= e) return;
    int w64 = is_w64((const int*)ei);
    int src = (int)getIdx(ei, i, w64);
    int dst = (int)getIdx(ei, (size_t)e + i, w64);
    int t = (int)getIdx(et, i, w64);
    atomicAdd(&g_cnt[dst * r + t], 1);
    atomicAdd(&g_hist[(src >> 7) * r + t], 1);
}

// ---------------- exclusive scan over nb buckets (single block) ----------------
__global__ void s_scan(int nb) {
    __shared__ int part[1024];
    int chunk = (nb + 1023) / 1024;
    int beg = threadIdx.x * chunk;
    int end = min(beg + chunk, nb);
    int s = 0;
    for (int i = beg; i < end; i++) s += g_hist[i];
    part[threadIdx.x] = s;
    __syncthreads();
    for (int off = 1; off < 1024; off <<= 1) {
        int v = (threadIdx.x >= off) ? part[threadIdx.x - off] : 0;
        __syncthreads();
        part[threadIdx.x] += v;
        __syncthreads();
    }
    int run = (threadIdx.x == 0) ? 0 : part[threadIdx.x - 1];
    for (int i = beg; i < end; i++) {
        int h = g_hist[i];
        g_seg[i] = run;
        g_cur[i] = run;
        run += h;
    }
    if (threadIdx.x == 0) g_seg[nb] = part[1023];
}

// ---------------- place edges into buckets (one edge / thread — measured best) ----------------
__global__ void s_place(const void* __restrict__ ei, const void* __restrict__ et, int e, int r) {
    int i = blockIdx.x * blockDim.x + threadIdx.x;
    if (i >= e) return;
    int w64 = is_w64((const int*)ei);
    int src = (int)getIdx(ei, i, w64);
    int dst = (int)getIdx(ei, (size_t)e + i, w64);
    int t = (int)getIdx(et, i, w64);
    int pos = atomicAdd(&g_cur[(src >> 7) * r + t], 1);
    g_epk[pos] = (uint32_t)dst | ((uint32_t)(src & 127) << 17);
    int c = g_cnt[dst * r + t];
    g_enorm[pos] = 1.0f / (float)(c > 0 ? c : 1);
}

// ---------------- HMMA fp16 GEMM, 3-stage cp.async pipeline, fused scatter ----------------
// MODE 0 (grid 1 x mtiles): g_A1 @ W1T root block -> g_yroot   (no edge data needed)
// MODE 1 (grid 8 x mtiles): g_A1 @ W1T relation bx -> smem -> atomic scatter into g_agg
// MODE 2 (grid 2 x mtiles): g_A2 @ g_W2T (d_out zeroed in prep)
//   bx 0 (w_root half): red.add (acc + bias) into Cext rows
//   bx 1 (w_rel half):  tile -> smem -> atomic scatter into Cext over edges
template <int MODE>
__global__ __launch_bounds__(256, 2) void k_gemm_mma(float* __restrict__ Cext,
                                                     const float* __restrict__ bias, int M,
                                                     int r) {
    const __half* A  = (MODE == 2) ? g_A2 : g_A1;
    const __half* Bw = (MODE == 2) ? g_W2T : g_W1T;
    const int nB0 = (MODE == 0) ? MAXR * DD : blockIdx.x * 128;

    extern __shared__ char dsm[];
    uint32_t s0 = smem_u32(dsm);   // 3 slots x [A 16K | B 16K] = 96KB

    int tid = threadIdx.x;
    int wid = tid >> 5, lane = tid & 31;
    int wm = wid & 3, wn = wid >> 2;
    int m0 = blockIdx.y * 128;

    float acc[2][8][4];
#pragma unroll
    for (int i = 0; i < 2; i++)
#pragma unroll
        for (int j = 0; j < 8; j++)
#pragma unroll
            for (int q = 0; q < 4; q++) acc[i][j][q] = 0.f;

    auto load_tile = [&](int kt, int slot) {
        uint32_t sa = s0 + slot * 32768, sb = sa + 16384;
#pragma unroll
        for (int i = 0; i < 4; i++) {
            int id = i * 256 + tid;
            int row = id >> 3, c8 = id & 7;
            uint32_t soff = row * 128 + ((c8 ^ (row & 7)) * 16);
            const void* gA = A + (size_t)(m0 + row) * KS + kt * 64 + c8 * 8;
            int szA = (m0 + row < M) ? 16 : 0;
            asm volatile("cp.async.ca.shared.global [%0], [%1], 16, %2;" ::"r"(sa + soff),
                         "l"(gA), "r"(szA)
                         : "memory");
            const void* gB = Bw + (size_t)(nB0 + row) * KS + kt * 64 + c8 * 8;
            asm volatile("cp.async.ca.shared.global [%0], [%1], 16;" ::"r"(sb + soff), "l"(gB)
                         : "memory");
        }
        asm volatile("cp.async.commit_group;" ::: "memory");
    };

    uint32_t fa[2][2][4];
    uint32_t fb[2][8][2];

    auto ldsm_stage = [&](uint32_t sA, uint32_t sB, int k16, int st) {
#pragma unroll
        for (int mi = 0; mi < 2; mi++) {
            int row = wm * 32 + mi * 16 + (lane & 15);
            int g = k16 * 2 + (lane >> 4);
            uint32_t addr = sA + row * 128 + ((g ^ (row & 7)) * 16);
            asm volatile("ldmatrix.sync.aligned.m8n8.x4.shared.b16 {%0,%1,%2,%3}, [%4];"
                         : "=r"(fa[st][mi][0]), "=r"(fa[st][mi][1]), "=r"(fa[st][mi][2]),
                           "=r"(fa[st][mi][3])
                         : "r"(addr));
        }
#pragma unroll
        for (int nq = 0; nq < 4; nq++) {
            int row = wn * 64 + nq * 16 + (lane & 15);
            int g = k16 * 2 + (lane >> 4);
            uint32_t addr = sB + row * 128 + ((g ^ (row & 7)) * 16);
            uint32_t r0, r1, r2, r3;
            asm volatile("ldmatrix.sync.aligned.m8n8.x4.shared.b16 {%0,%1,%2,%3}, [%4];"
                         : "=r"(r0), "=r"(r1), "=r"(r2), "=r"(r3)
                         : "r"(addr));
            fb[st][nq * 2 + 0][0] = r0; fb[st][nq * 2 + 0][1] = r2;
            fb[st][nq * 2 + 1][0] = r1; fb[st][nq * 2 + 1][1] = r3;
        }
    };
    auto hmma_stage = [&](int st) {
#pragma unroll
        for (int mi = 0; mi < 2; mi++)
#pragma unroll
            for (int ni = 0; ni < 8; ni++)
                asm volatile(
                    "mma.sync.aligned.m16n8k16.row.col.f32.f16.f16.f32 "
                    "{%0,%1,%2,%3}, {%4,%5,%6,%7}, {%8,%9}, {%0,%1,%2,%3};"
                    : "+f"(acc[mi][ni][0]), "+f"(acc[mi][ni][1]), "+f"(acc[mi][ni][2]),
                      "+f"(acc[mi][ni][3])
                    : "r"(fa[st][mi][0]), "r"(fa[st][mi][1]), "r"(fa[st][mi][2]),
                      "r"(fa[st][mi][3]), "r"(fb[st][ni][0]), "r"(fb[st][ni][1]));
    };

    const int NK = KS / 64;   // 4
    // 3-slot pipeline: prologue fills stages 0,1; each iter waits stage kt,
    // syncs once, prefetches stage kt+2 into slot (kt+2)%3 (its previous
    // occupant, stage kt-1, is protected by this iter's sync).
    load_tile(0, 0);
    load_tile(1, 1);
    for (int kt = 0; kt < NK; kt++) {
        asm volatile("cp.async.wait_group 1;" ::: "memory");
        __syncthreads();
        if (kt + 2 < NK)
            load_tile(kt + 2, (kt + 2) % 3);
        else
            asm volatile("cp.async.commit_group;" ::: "memory");   // uniform group count

        uint32_t sA = s0 + (kt % 3) * 32768, sB = sA + 16384;
        ldsm_stage(sA, sB, 0, 0);
#pragma unroll
        for (int k16 = 0; k16 < 4; k16++) {
            if (k16 < 3) ldsm_stage(sA, sB, k16 + 1, (k16 + 1) & 1);
            hmma_stage(k16 & 1);
        }
    }
    __syncthreads();   // protect smem reuse by the scatter epilogue

    if (MODE == 0) {
        // root block -> g_yroot (plain stores; g_yroot private to layer 1)
#pragma unroll
        for (int mi = 0; mi < 2; mi++) {
            int r0 = m0 + wm * 32 + mi * 16 + (lane >> 2);
#pragma unroll
            for (int ni = 0; ni < 8; ni++) {
                int ct = wn * 64 + ni * 8 + (lane & 3) * 2;
                if (r0 < M)
                    *(float2*)(g_yroot + (size_t)r0 * DD + ct) =
                        make_float2(acc[mi][ni][0], acc[mi][ni][1]);
                if (r0 + 8 < M)
                    *(float2*)(g_yroot + (size_t)(r0 + 8) * DD + ct) =
                        make_float2(acc[mi][ni][2], acc[mi][ni][3]);
            }
        }
    } else if (MODE == 2 && blockIdx.x == 0) {
        // w_root half: atomically add acc + bias into d_out (zeroed in prep)
#pragma unroll
        for (int mi = 0; mi < 2; mi++) {
            int r0 = m0 + wm * 32 + mi * 16 + (lane >> 2);
#pragma unroll
            for (int ni = 0; ni < 8; ni++) {
                int ct = wn * 64 + ni * 8 + (lane & 3) * 2;
                float b0 = bias[ct], b1 = bias[ct + 1];
                if (r0 < M) {
                    float* p = Cext + (size_t)r0 * DD + ct;
                    asm volatile("red.global.add.v2.f32 [%0], {%1,%2};" ::"l"(p),
                                 "f"(acc[mi][ni][0] + b0), "f"(acc[mi][ni][1] + b1)
                                 : "memory");
                }
                if (r0 + 8 < M) {
                    float* p = Cext + (size_t)(r0 + 8) * DD + ct;
                    asm volatile("red.global.add.v2.f32 [%0], {%1,%2};" ::"l"(p),
                                 "f"(acc[mi][ni][2] + b0), "f"(acc[mi][ni][3] + b1)
                                 : "memory");
                }
            }
        }
    } else {
        // scatter epilogue: tile -> smem, walk edge bucket, atomic-add rows (pipelined)
        float* ts = (float*)dsm;   // [128][132]
#pragma unroll
        for (int mi = 0; mi < 2; mi++) {
            int r0 = wm * 32 + mi * 16 + (lane >> 2);
#pragma unroll
            for (int ni = 0; ni < 8; ni++) {
                int ct = wn * 64 + ni * 8 + (lane & 3) * 2;
                *(float2*)&ts[r0 * 132 + ct] = make_float2(acc[mi][ni][0], acc[mi][ni][1]);
                *(float2*)&ts[(r0 + 8) * 132 + ct] =
                    make_float2(acc[mi][ni][2], acc[mi][ni][3]);
            }
        }
        __syncthreads();
        int s, eN;
        if (MODE == 1) {
            int key = blockIdx.y * r + blockIdx.x;
            s = g_seg[key];
            eN = g_seg[key + 1];
        } else {
            s = g_seg[blockIdx.y * r];
            eN = g_seg[blockIdx.y * r + r];
        }
        float* target = (MODE == 1) ? g_agg : Cext;
        int ie = s + wid;
        uint32_t pk = 0;
        float nm = 1.0f;
        if (ie < eN) {
            pk = g_epk[ie];
            if (MODE == 1) nm = g_enorm[ie];
        }
        while (ie < eN) {
            int nxt = ie + 8;
            uint32_t pk2 = 0;
            float nm2 = 1.0f;
            if (nxt < eN) {
                pk2 = g_epk[nxt];
                if (MODE == 1) nm2 = g_enorm[nxt];
            }
            int dst = pk & 0x1FFFF, sl = pk >> 17;
            float4 v = *(float4*)&ts[sl * 132 + lane * 4];
            float* p = target + (size_t)dst * DD + lane * 4;
            asm volatile("red.global.add.v4.f32 [%0], {%1,%2,%3,%4};" ::"l"(p), "f"(v.x * nm),
                         "f"(v.y * nm), "f"(v.z * nm), "f"(v.w * nm)
                         : "memory");
            pk = pk2;
            nm = nm2;
            ie = nxt;
        }
    }
}

// ---------------- compose h1 = agg + yroot + bias1 -> 2-term split into A2 ----------------
__global__ void k_compose(const float* __restrict__ bias1, int n) {
    int i = blockIdx.x * blockDim.x + threadIdx.x;
    if (i >= n * 16) return;
    int nn = i >> 4, g = i & 15;
    const float4* pa = (const float4*)(g_agg + (size_t)nn * DD + g * 8);
    const float4* py = (const float4*)(g_yroot + (size_t)nn * DD + g * 8);
    const float4* pb = (const float4*)(bias1 + g * 8);
    float4 a0 = pa[0], a1 = pa[1], y0 = py[0], y1 = py[1], b0 = pb[0], b1 = pb[1];
    float4 h0 = make_float4(a0.x + y0.x + b0.x, a0.y + y0.y + b0.y, a0.z + y0.z + b0.z,
                            a0.w + y0.w + b0.w);
    float4 h1 = make_float4(a1.x + y1.x + b1.x, a1.y + y1.y + b1.y, a1.z + y1.z + b1.z,
                            a1.w + y1.w + b1.w);
    uint4 hi, lo;
    split8h(h0, h1, hi, lo);
    __half* base = g_A2 + (size_t)nn * KS + g * 8;
    *(uint4*)(base) = hi;
    *(uint4*)(base + 128) = lo;
}

extern "C" void kernel_launch(void* const* d_in, const int* in_sizes, int n_in,
                              void* d_out, int out_size) {
    const float* x      = (const float*)d_in[0];
    const void*  ei     = d_in[1];
    const void*  et     = d_in[2];
    const float* basis  = (const float*)d_in[3];
    const float* comp   = (const float*)d_in[4];
    const float* root   = (const float*)d_in[5];
    const float* bias1  = (const float*)d_in[6];
    const float* w_rel  = (const float*)d_in[7];
    const float* b_rel  = (const float*)d_in[8];
    const float* w_root = (const float*)d_in[9];

    int n = in_sizes[0] / DD;
    int e = in_sizes[2];
    int b = in_sizes[3] / (DD * DD);
    int r = in_sizes[4] / b;   // 8

    int mtiles = (n + 127) / 128;
    int nb = mtiles * r;
    const int SMEM = 98304;   // 3 pipeline slots x 32KB
    cudaFuncSetAttribute(k_gemm_mma<0>, cudaFuncAttributeMaxDynamicSharedMemorySize, SMEM);
    cudaFuncSetAttribute(k_gemm_mma<1>, cudaFuncAttributeMaxDynamicSharedMemorySize, SMEM);
    cudaFuncSetAttribute(k_gemm_mma<2>, cudaFuncAttributeMaxDynamicSharedMemorySize, SMEM);

    // Lazily-created side stream + events (host-side objects only; identical
    // GPU work / graph topology on every call).
    static cudaStream_t s2 = nullptr;
    static cudaEvent_t evFork = nullptr, evJoin = nullptr;
    if (!s2) {
        cudaStreamCreateWithFlags(&s2, cudaStreamNonBlocking);
        cudaEventCreateWithFlags(&evFork, cudaEventDisableTiming);
        cudaEventCreateWithFlags(&evJoin, cudaEventDisableTiming);
    }
    bool fork = (s2 != nullptr && evFork != nullptr && evJoin != nullptr);
    cudaStream_t sb = fork ? s2 : (cudaStream_t)0;

    // Branch A (stream 0): prep -> root GEMM (no edge dependency)
    // Branch B (side):     zero cnt/hist -> count -> scan -> place
    if (fork) {
        cudaEventRecord(evFork, 0);
        cudaStreamWaitEvent(s2, evFork, 0);
    }
    k_zero_cnt_hist<<<((n * r + 3) / 4 + 255) / 256, 256, 0, sb>>>(n, r, nb);
    {
        int total = n * 32 + (NOUT1 + 256) * DD + n * 16;
        k_prep<<<(total + 255) / 256, 256>>>(x, basis, comp, root, w_rel, w_root,
                                             (float*)d_out, n, b);
    }
    k_count_hist<<<(e + 255) / 256, 256, 0, sb>>>(ei, et, e, r);
    k_gemm_mma<0><<<dim3(1, mtiles), 256, SMEM>>>(nullptr, nullptr, n, r);   // branch A
    s_scan<<<1, 1024, 0, sb>>>(nb);
    s_place<<<(e + 255) / 256, 256, 0, sb>>>(ei, et, e, r);
    if (fork) {
        cudaEventRecord(evJoin, s2);
        cudaStreamWaitEvent((cudaStream_t)0, evJoin, 0);
    }

    // relations GEMM (needs edges + A1/W1T + zeroed agg)
    k_gemm_mma<1><<<dim3(MAXR, mtiles), 256, SMEM>>>(nullptr, nullptr, n, r);

    // compose h1
    k_compose<<<(n * 16 + 255) / 256, 256>>>(bias1, n);

    // layer-2 both halves in one launch (all-atomic into zeroed d_out)
    k_gemm_mma<2><<<dim3(2, mtiles), 256, SMEM>>>((float*)d_out, b_rel, n, r);
}

// round 14
// speedup vs baseline: 1.1211x; 1.1211x over previous
#include <cuda_runtime.h>
#include <cuda_fp16.h>
#include <cstdint>

// Problem constants
#define DD    128
#define MAXN  50000
#define MAXR  8
#define KS    256     // storage K: [hi | lo] blocks of 128
#define NOUT1 1152    // R*D + D (root)
#define MAXE  600000
#define MAXT  ((MAXN + 127) / 128)
#define MAXB  (MAXT * MAXR)

// ---------------- device scratch ----------------
__device__ __half   g_A1  [(size_t)MAXN * KS];   // split X (fp16)
__device__ __half   g_A2  [(size_t)MAXN * KS];   // split h1 (fp16)
__device__ __half   g_W1T [NOUT1 * KS];          // layer-1 B operand [Nout, K]
__device__ __half   g_W2T [256 * KS];            // layer-2 B operand [root|rel]
__device__ float    g_yroot[(size_t)MAXN * DD];
__device__ float    g_agg  [(size_t)MAXN * DD];
__device__ int      g_cnt [MAXN * MAXR];
__device__ int      g_hist[MAXB];
__device__ int      g_seg [MAXB + 1];
__device__ int      g_cur [MAXB];
__device__ uint32_t g_epk [MAXE];   // dst | (src&127)<<17
__device__ float    g_enorm[MAXE];

__device__ __forceinline__ uint32_t smem_u32(const void* p) {
    uint32_t a;
    asm("{ .reg .u64 t; cvta.to.shared.u64 t, %1; cvt.u32.u64 %0, t; }" : "=r"(a) : "l"(p));
    return a;
}

// ---------------- inline index dtype detection ----------------
__device__ __forceinline__ int is_w64(const int* __restrict__ ei32) {
    return ((ei32[1] | ei32[3] | ei32[5] | ei32[7]) == 0) ? 1 : 0;
}
__device__ __forceinline__ long long getIdx(const void* __restrict__ p, size_t i, int w64) {
    if (w64) return ((const long long*)p)[i];
    return (long long)((const int*)p)[i];
}

// ---------------- 8-wide fp16 split pack ----------------
union Pack8h {
    __half b[8];
    uint4 u;
};
__device__ __forceinline__ void split8h(float4 a, float4 c, uint4& hi, uint4& lo) {
    float f[8] = {a.x, a.y, a.z, a.w, c.x, c.y, c.z, c.w};
    Pack8h H, L;
#pragma unroll
    for (int j = 0; j < 8; j++) {
        __half h = __float2half_rn(f[j]);
        H.b[j] = h;
        L.b[j] = __float2half_rn(f[j] - __half2float(h));
    }
    hi = H.u;
    lo = L.u;
}

// ---------------- branch-A prep: zero agg/d_out | build weights | split X ----------------
__global__ void k_prep(const float* __restrict__ x, const float* __restrict__ basis,
                       const float* __restrict__ comp, const float* __restrict__ root,
                       const float* __restrict__ w_rel, const float* __restrict__ w_root,
                       float* __restrict__ dout, int n, int B_) {
    int id = blockIdx.x * blockDim.x + threadIdx.x;
    const int Z = n * 32;                  // zero range (float4 over N*128)
    const int W = (NOUT1 + 256) * DD;      // weight elements
    if (id < Z) {
        ((float4*)g_agg)[id] = make_float4(0.f, 0.f, 0.f, 0.f);
        ((float4*)dout)[id] = make_float4(0.f, 0.f, 0.f, 0.f);
    } else if (id < Z + W) {
        int idx = id - Z;
        const int nrel = MAXR * DD * DD;       // 131072
        const int n1 = NOUT1 * DD;             // 147456
        if (idx < nrel) {
            int o = idx & 127, c = (idx >> 7) & 127, rr = idx >> 14;
            float w = 0.f;
            for (int b = 0; b < B_; b++)
                w += comp[rr * B_ + b] * basis[((size_t)b * DD + c) * DD + o];
            __half hi = __float2half_rn(w);
            int j = rr * DD + o;
            g_W1T[j * KS + c] = hi;
            g_W1T[j * KS + 128 + c] = hi;
        } else if (idx < n1) {
            int i2 = idx - nrel;
            int o = i2 & 127, c = (i2 >> 7) & 127;
            __half hi = __float2half_rn(root[c * DD + o]);
            int j = MAXR * DD + o;
            g_W1T[j * KS + c] = hi;
            g_W1T[j * KS + 128 + c] = hi;
        } else {
            int t = idx - n1;
            int o = t >> 7, c = t & 127;   // o<128: w_root row o ; o>=128: w_rel row o-128
            float w = (o < DD) ? w_root[o * DD + c] : w_rel[(o - DD) * DD + c];
            __half hi = __float2half_rn(w);
            g_W2T[o * KS + c] = hi;
            g_W2T[o * KS + 128 + c] = hi;
        }
    } else if (id < Z + W + n * 16) {
        int i = id - Z - W;
        int nn = i >> 4, g = i & 15;
        const float4* src = (const float4*)(x + (size_t)nn * DD + g * 8);
        uint4 hi, lo;
        split8h(src[0], src[1], hi, lo);
        __half* base = g_A1 + (size_t)nn * KS + g * 8;
        *(uint4*)(base) = hi;
        *(uint4*)(base + 128) = lo;
    }
}

// ---------------- branch-B zero: cnt + hist (owned by bucketing chain) ----------------
__global__ void k_zero_cnt_hist(int n, int r, int nb) {
    int i = blockIdx.x * blockDim.x + threadIdx.x;
    if (i < (n * r + 3) / 4) ((int4*)g_cnt)[i] = make_int4(0, 0, 0, 0);
    if (i < nb) g_hist[i] = 0;
}

// ---------------- per-(dst,rel) count + per-(srcblk,rel) histogram ----------------
__global__ void k_count_hist(const void* __restrict__ ei, const void* __restrict__ et, int e,
                             int r) {
    int i = blockIdx.x * blockDim.x + threadIdx.x;
    if (i >= e) return;
    int w64 = is_w64((const int*)ei);
    int src = (int)getIdx(ei, i, w64);
    int dst = (int)getIdx(ei, (size_t)e + i, w64);
    int t = (int)getIdx(et, i, w64);
    atomicAdd(&g_cnt[dst * r + t], 1);
    atomicAdd(&g_hist[(src >> 7) * r + t], 1);
}

// ---------------- exclusive scan over nb buckets (single block) ----------------
__global__ void s_scan(int nb) {
    __shared__ int part[1024];
    int chunk = (nb + 1023) / 1024;
    int beg = threadIdx.x * chunk;
    int end = min(beg + chunk, nb);
    int s = 0;
    for (int i = beg; i < end; i++) s += g_hist[i];
    part[threadIdx.x] = s;
    __syncthreads();
    for (int off = 1; off < 1024; off <<= 1) {
        int v = (threadIdx.x >= off) ? part[threadIdx.x - off] : 0;
        __syncthreads();
        part[threadIdx.x] += v;
        __syncthreads();
    }
    int run = (threadIdx.x == 0) ? 0 : part[threadIdx.x - 1];
    for (int i = beg; i < end; i++) {
        int h = g_hist[i];
        g_seg[i] = run;
        g_cur[i] = run;
        run += h;
    }
    if (threadIdx.x == 0) g_seg[nb] = part[1023];
}

// ---------------- place edges into buckets (one edge / thread — measured best) ----------------
__global__ void s_place(const void* __restrict__ ei, const void* __restrict__ et, int e, int r) {
    int i = blockIdx.x * blockDim.x + threadIdx.x;
    if (i >= e) return;
    int w64 = is_w64((const int*)ei);
    int src = (int)getIdx(ei, i, w64);
    int dst = (int)getIdx(ei, (size_t)e + i, w64);
    int t = (int)getIdx(et, i, w64);
    int pos = atomicAdd(&g_cur[(src >> 7) * r + t], 1);
    g_epk[pos] = (uint32_t)dst | ((uint32_t)(src & 127) << 17);
    int c = g_cnt[dst * r + t];
    g_enorm[pos] = 1.0f / (float)(c > 0 ? c : 1);
}

// ---------------- HMMA fp16 GEMM (double-buffered) with fused scatter epilogues ----------------
// MODE 0, KT=256 (grid 1 x mtiles): g_A1 @ W1T root block -> g_yroot
// MODE 1, KT=128 (grid 8 x mtiles): x_hi @ W_hi relation bx -> smem -> scatter into g_agg
// MODE 2, KT=256 (grid 2 x mtiles): g_A2 @ g_W2T (d_out zeroed in prep)
//   bx 0 (w_root half): red.add (acc + bias) into Cext rows
//   bx 1 (w_rel half):  tile -> smem -> atomic scatter into Cext over edges
template <int MODE, int KT>
__global__ __launch_bounds__(256, 2) void k_gemm_mma(float* __restrict__ Cext,
                                                     const float* __restrict__ bias, int M,
                                                     int r) {
    const __half* A  = (MODE == 2) ? g_A2 : g_A1;
    const __half* Bw = (MODE == 2) ? g_W2T : g_W1T;
    const int nB0 = (MODE == 0) ? MAXR * DD : blockIdx.x * 128;

    extern __shared__ char dsm[];
    uint32_t s0 = smem_u32(dsm);   // [As0 16K][Bs0 16K][As1 16K][Bs1 16K]

    int tid = threadIdx.x;
    int wid = tid >> 5, lane = tid & 31;
    int wm = wid & 3, wn = wid >> 2;
    int m0 = blockIdx.y * 128;

    float acc[2][8][4];
#pragma unroll
    for (int i = 0; i < 2; i++)
#pragma unroll
        for (int j = 0; j < 8; j++)
#pragma unroll
            for (int q = 0; q < 4; q++) acc[i][j][q] = 0.f;

    auto load_tile = [&](int kt, int buf) {
        uint32_t sa = s0 + buf * 32768, sb = sa + 16384;
#pragma unroll
        for (int i = 0; i < 4; i++) {
            int id = i * 256 + tid;
            int row = id >> 3, c8 = id & 7;
            uint32_t soff = row * 128 + ((c8 ^ (row & 7)) * 16);
            const void* gA = A + (size_t)(m0 + row) * KS + kt * 64 + c8 * 8;
            int szA = (m0 + row < M) ? 16 : 0;
            asm volatile("cp.async.ca.shared.global [%0], [%1], 16, %2;" ::"r"(sa + soff),
                         "l"(gA), "r"(szA)
                         : "memory");
            const void* gB = Bw + (size_t)(nB0 + row) * KS + kt * 64 + c8 * 8;
            asm volatile("cp.async.ca.shared.global [%0], [%1], 16;" ::"r"(sb + soff), "l"(gB)
                         : "memory");
        }
        asm volatile("cp.async.commit_group;" ::: "memory");
    };

    uint32_t fa[2][2][4];
    uint32_t fb[2][8][2];

    auto ldsm_stage = [&](uint32_t sA, uint32_t sB, int k16, int st) {
#pragma unroll
        for (int mi = 0; mi < 2; mi++) {
            int row = wm * 32 + mi * 16 + (lane & 15);
            int g = k16 * 2 + (lane >> 4);
            uint32_t addr = sA + row * 128 + ((g ^ (row & 7)) * 16);
            asm volatile("ldmatrix.sync.aligned.m8n8.x4.shared.b16 {%0,%1,%2,%3}, [%4];"
                         : "=r"(fa[st][mi][0]), "=r"(fa[st][mi][1]), "=r"(fa[st][mi][2]),
                           "=r"(fa[st][mi][3])
                         : "r"(addr));
        }
#pragma unroll
        for (int nq = 0; nq < 4; nq++) {
            int row = wn * 64 + nq * 16 + (lane & 15);
            int g = k16 * 2 + (lane >> 4);
            uint32_t addr = sB + row * 128 + ((g ^ (row & 7)) * 16);
            uint32_t r0, r1, r2, r3;
            asm volatile("ldmatrix.sync.aligned.m8n8.x4.shared.b16 {%0,%1,%2,%3}, [%4];"
                         : "=r"(r0), "=r"(r1), "=r"(r2), "=r"(r3)
                         : "r"(addr));
            fb[st][nq * 2 + 0][0] = r0; fb[st][nq * 2 + 0][1] = r2;
            fb[st][nq * 2 + 1][0] = r1; fb[st][nq * 2 + 1][1] = r3;
        }
    };
    auto hmma_stage = [&](int st) {
#pragma unroll
        for (int mi = 0; mi < 2; mi++)
#pragma unroll
            for (int ni = 0; ni < 8; ni++)
                asm volatile(
                    "mma.sync.aligned.m16n8k16.row.col.f32.f16.f16.f32 "
                    "{%0,%1,%2,%3}, {%4,%5,%6,%7}, {%8,%9}, {%0,%1,%2,%3};"
                    : "+f"(acc[mi][ni][0]), "+f"(acc[mi][ni][1]), "+f"(acc[mi][ni][2]),
                      "+f"(acc[mi][ni][3])
                    : "r"(fa[st][mi][0]), "r"(fa[st][mi][1]), "r"(fa[st][mi][2]),
                      "r"(fa[st][mi][3]), "r"(fb[st][ni][0]), "r"(fb[st][ni][1]));
    };

    const int NK = KT / 64;
    load_tile(0, 0);
    int buf = 0;
    for (int kt = 0; kt < NK; kt++) {
        if (kt + 1 < NK)
            load_tile(kt + 1, buf ^ 1);
        else
            asm volatile("cp.async.commit_group;" ::: "memory");
        asm volatile("cp.async.wait_group 1;" ::: "memory");
        __syncthreads();

        uint32_t sA = s0 + buf * 32768, sB = sA + 16384;
        ldsm_stage(sA, sB, 0, 0);
#pragma unroll
        for (int k16 = 0; k16 < 4; k16++) {
            if (k16 < 3) ldsm_stage(sA, sB, k16 + 1, (k16 + 1) & 1);
            hmma_stage(k16 & 1);
        }
        __syncthreads();
        buf ^= 1;
    }

    if (MODE == 0) {
        // root block -> g_yroot (plain stores; g_yroot private to layer 1)
#pragma unroll
        for (int mi = 0; mi < 2; mi++) {
            int r0 = m0 + wm * 32 + mi * 16 + (lane >> 2);
#pragma unroll
            for (int ni = 0; ni < 8; ni++) {
                int ct = wn * 64 + ni * 8 + (lane & 3) * 2;
                if (r0 < M)
                    *(float2*)(g_yroot + (size_t)r0 * DD + ct) =
                        make_float2(acc[mi][ni][0], acc[mi][ni][1]);
                if (r0 + 8 < M)
                    *(float2*)(g_yroot + (size_t)(r0 + 8) * DD + ct) =
                        make_float2(acc[mi][ni][2], acc[mi][ni][3]);
            }
        }
    } else if (MODE == 2 && blockIdx.x == 0) {
        // w_root half: atomically add acc + bias into d_out (zeroed in prep)
#pragma unroll
        for (int mi = 0; mi < 2; mi++) {
            int r0 = m0 + wm * 32 + mi * 16 + (lane >> 2);
#pragma unroll
            for (int ni = 0; ni < 8; ni++) {
                int ct = wn * 64 + ni * 8 + (lane & 3) * 2;
                float b0 = bias[ct], b1 = bias[ct + 1];
                if (r0 < M) {
                    float* p = Cext + (size_t)r0 * DD + ct;
                    asm volatile("red.global.add.v2.f32 [%0], {%1,%2};" ::"l"(p),
                                 "f"(acc[mi][ni][0] + b0), "f"(acc[mi][ni][1] + b1)
                                 : "memory");
                }
                if (r0 + 8 < M) {
                    float* p = Cext + (size_t)(r0 + 8) * DD + ct;
                    asm volatile("red.global.add.v2.f32 [%0], {%1,%2};" ::"l"(p),
                                 "f"(acc[mi][ni][2] + b0), "f"(acc[mi][ni][3] + b1)
                                 : "memory");
                }
            }
        }
    } else {
        // scatter epilogue: tile -> smem, walk edge bucket, atomic-add rows (pipelined)
        float* ts = (float*)dsm;   // [128][132]
#pragma unroll
        for (int mi = 0; mi < 2; mi++) {
            int r0 = wm * 32 + mi * 16 + (lane >> 2);
#pragma unroll
            for (int ni = 0; ni < 8; ni++) {
                int ct = wn * 64 + ni * 8 + (lane & 3) * 2;
                *(float2*)&ts[r0 * 132 + ct] = make_float2(acc[mi][ni][0], acc[mi][ni][1]);
                *(float2*)&ts[(r0 + 8) * 132 + ct] =
                    make_float2(acc[mi][ni][2], acc[mi][ni][3]);
            }
        }
        __syncthreads();
        int s, eN;
        if (MODE == 1) {
            int key = blockIdx.y * r + blockIdx.x;
            s = g_seg[key];
            eN = g_seg[key + 1];
        } else {
            s = g_seg[blockIdx.y * r];
            eN = g_seg[blockIdx.y * r + r];
        }
        float* target = (MODE == 1) ? g_agg : Cext;
        int ie = s + wid;
        uint32_t pk = 0;
        float nm = 1.0f;
        if (ie < eN) {
            pk = g_epk[ie];
            if (MODE == 1) nm = g_enorm[ie];
        }
        while (ie < eN) {
            int nxt = ie + 8;
            uint32_t pk2 = 0;
            float nm2 = 1.0f;
            if (nxt < eN) {
                pk2 = g_epk[nxt];
                if (MODE == 1) nm2 = g_enorm[nxt];
            }
            int dst = pk & 0x1FFFF, sl = pk >> 17;
            float4 v = *(float4*)&ts[sl * 132 + lane * 4];
            float* p = target + (size_t)dst * DD + lane * 4;
            asm volatile("red.global.add.v4.f32 [%0], {%1,%2,%3,%4};" ::"l"(p), "f"(v.x * nm),
                         "f"(v.y * nm), "f"(v.z * nm), "f"(v.w * nm)
                         : "memory");
            pk = pk2;
            nm = nm2;
            ie = nxt;
        }
    }
}

// ---------------- compose h1 = agg + yroot + bias1 -> 2-term split into A2 ----------------
__global__ void k_compose(const float* __restrict__ bias1, int n) {
    int i = blockIdx.x * blockDim.x + threadIdx.x;
    if (i >= n * 16) return;
    int nn = i >> 4, g = i & 15;
    const float4* pa = (const float4*)(g_agg + (size_t)nn * DD + g * 8);
    const float4* py = (const float4*)(g_yroot + (size_t)nn * DD + g * 8);
    const float4* pb = (const float4*)(bias1 + g * 8);
    float4 a0 = pa[0], a1 = pa[1], y0 = py[0], y1 = py[1], b0 = pb[0], b1 = pb[1];
    float4 h0 = make_float4(a0.x + y0.x + b0.x, a0.y + y0.y + b0.y, a0.z + y0.z + b0.z,
                            a0.w + y0.w + b0.w);
    float4 h1 = make_float4(a1.x + y1.x + b1.x, a1.y + y1.y + b1.y, a1.z + y1.z + b1.z,
                            a1.w + y1.w + b1.w);
    uint4 hi, lo;
    split8h(h0, h1, hi, lo);
    __half* base = g_A2 + (size_t)nn * KS + g * 8;
    *(uint4*)(base) = hi;
    *(uint4*)(base + 128) = lo;
}

extern "C" void kernel_launch(void* const* d_in, const int* in_sizes, int n_in,
                              void* d_out, int out_size) {
    const float* x      = (const float*)d_in[0];
    const void*  ei     = d_in[1];
    const void*  et     = d_in[2];
    const float* basis  = (const float*)d_in[3];
    const float* comp   = (const float*)d_in[4];
    const float* root   = (const float*)d_in[5];
    const float* bias1  = (const float*)d_in[6];
    const float* w_rel  = (const float*)d_in[7];
    const float* b_rel  = (const float*)d_in[8];
    const float* w_root = (const float*)d_in[9];

    int n = in_sizes[0] / DD;
    int e = in_sizes[2];
    int b = in_sizes[3] / (DD * DD);
    int r = in_sizes[4] / b;   // 8

    int mtiles = (n + 127) / 128;
    int nb = mtiles * r;
    const int SMEM = 69632;
    cudaFuncSetAttribute(k_gemm_mma<0, 256>, cudaFuncAttributeMaxDynamicSharedMemorySize, SMEM);
    cudaFuncSetAttribute(k_gemm_mma<1, 128>, cudaFuncAttributeMaxDynamicSharedMemorySize, SMEM);
    cudaFuncSetAttribute(k_gemm_mma<2, 256>, cudaFuncAttributeMaxDynamicSharedMemorySize, SMEM);

    // Lazily-created side stream + events (host-side objects only; identical
    // GPU work / graph topology on every call).
    static cudaStream_t s2 = nullptr;
    static cudaEvent_t evFork = nullptr, evJoin = nullptr;
    if (!s2) {
        cudaStreamCreateWithFlags(&s2, cudaStreamNonBlocking);
        cudaEventCreateWithFlags(&evFork, cudaEventDisableTiming);
        cudaEventCreateWithFlags(&evJoin, cudaEventDisableTiming);
    }
    bool fork = (s2 != nullptr && evFork != nullptr && evJoin != nullptr);
    cudaStream_t sb = fork ? s2 : (cudaStream_t)0;

    // Branch A (stream 0): prep -> root GEMM (no edge dependency)
    // Branch B (side):     zero cnt/hist -> count -> scan -> place
    if (fork) {
        cudaEventRecord(evFork, 0);
        cudaStreamWaitEvent(s2, evFork, 0);
    }
    k_zero_cnt_hist<<<((n * r + 3) / 4 + 255) / 256, 256, 0, sb>>>(n, r, nb);
    {
        int total = n * 32 + (NOUT1 + 256) * DD + n * 16;
        k_prep<<<(total + 255) / 256, 256>>>(x, basis, comp, root, w_rel, w_root,
                                             (float*)d_out, n, b);
    }
    k_count_hist<<<(e + 255) / 256, 256, 0, sb>>>(ei, et, e, r);
    k_gemm_mma<0, 256><<<dim3(1, mtiles), 256, SMEM>>>(nullptr, nullptr, n, r);   // branch A
    s_scan<<<1, 1024, 0, sb>>>(nb);
    s_place<<<(e + 255) / 256, 256, 0, sb>>>(ei, et, e, r);
    if (fork) {
        cudaEventRecord(evJoin, s2);
        cudaStreamWaitEvent((cudaStream_t)0, evJoin, 0);
    }

    // relations GEMM: x_hi only (K=128) — accuracy carried by W duplication model
    k_gemm_mma<1, 128><<<dim3(MAXR, mtiles), 256, SMEM>>>(nullptr, nullptr, n, r);

    // compose h1
    k_compose<<<(n * 16 + 255) / 256, 256>>>(bias1, n);

    // layer-2 both halves in one launch (all-atomic into zeroed d_out)
    k_gemm_mma<2, 256><<<dim3(2, mtiles), 256, SMEM>>>((float*)d_out, b_rel, n, r);
}

// round 15
// speedup vs baseline: 1.2372x; 1.1036x over previous
#include <cuda_runtime.h>
#include <cuda_fp16.h>
#include <cstdint>

// Problem constants
#define DD    128
#define MAXN  50000
#define MAXR  8
#define KH    128     // plain fp16 K for all GEMMs
#define NOUT1 1152    // R*D + D (root)
#define MAXE  600000
#define MAXT  ((MAXN + 127) / 128)
#define MAXB  (MAXT * MAXR)

// ---------------- device scratch ----------------
__device__ __half   g_A1  [(size_t)MAXN * KH];   // x (fp16)
__device__ __half   g_A2  [(size_t)MAXN * KH];   // h1 (fp16)
__device__ __half   g_W1T [NOUT1 * KH];          // layer-1 B operand [Nout, K]
__device__ __half   g_W2T [256 * KH];            // layer-2 B operand [root|rel]
__device__ float    g_yroot[(size_t)MAXN * DD];
__device__ float    g_agg  [(size_t)MAXN * DD];
__device__ int      g_cnt [MAXN * MAXR];
__device__ int      g_hist[MAXB];
__device__ int      g_seg [MAXB + 1];
__device__ int      g_cur [MAXB];
__device__ uint32_t g_epk [MAXE];   // dst | (src&127)<<17
__device__ float    g_enorm[MAXE];

__device__ __forceinline__ uint32_t smem_u32(const void* p) {
    uint32_t a;
    asm("{ .reg .u64 t; cvta.to.shared.u64 t, %1; cvt.u32.u64 %0, t; }" : "=r"(a) : "l"(p));
    return a;
}

// ---------------- inline index dtype detection ----------------
__device__ __forceinline__ int is_w64(const int* __restrict__ ei32) {
    return ((ei32[1] | ei32[3] | ei32[5] | ei32[7]) == 0) ? 1 : 0;
}
__device__ __forceinline__ long long getIdx(const void* __restrict__ p, size_t i, int w64) {
    if (w64) return ((const long long*)p)[i];
    return (long long)((const int*)p)[i];
}

// ---------------- 8-wide fp16 pack ----------------
union Pack8h {
    __half b[8];
    uint4 u;
};
__device__ __forceinline__ uint4 cvt8h(float4 a, float4 c) {
    float f[8] = {a.x, a.y, a.z, a.w, c.x, c.y, c.z, c.w};
    Pack8h H;
#pragma unroll
    for (int j = 0; j < 8; j++) H.b[j] = __float2half_rn(f[j]);
    return H.u;
}

// ---------------- branch-A prep: zero agg/d_out | build weights | convert X ----------------
__global__ void k_prep(const float* __restrict__ x, const float* __restrict__ basis,
                       const float* __restrict__ comp, const float* __restrict__ root,
                       const float* __restrict__ w_rel, const float* __restrict__ w_root,
                       float* __restrict__ dout, int n, int B_) {
    int id = blockIdx.x * blockDim.x + threadIdx.x;
    const int Z = n * 32;                  // zero range (float4 over N*128)
    const int W = (NOUT1 + 256) * DD;      // weight elements
    if (id < Z) {
        ((float4*)g_agg)[id] = make_float4(0.f, 0.f, 0.f, 0.f);
        ((float4*)dout)[id] = make_float4(0.f, 0.f, 0.f, 0.f);
    } else if (id < Z + W) {
        int idx = id - Z;
        const int nrel = MAXR * DD * DD;       // 131072
        const int n1 = NOUT1 * DD;             // 147456
        if (idx < nrel) {
            int o = idx & 127, c = (idx >> 7) & 127, rr = idx >> 14;
            float w = 0.f;
            for (int b = 0; b < B_; b++)
                w += comp[rr * B_ + b] * basis[((size_t)b * DD + c) * DD + o];
            g_W1T[(rr * DD + o) * KH + c] = __float2half_rn(w);
        } else if (idx < n1) {
            int i2 = idx - nrel;
            int o = i2 & 127, c = (i2 >> 7) & 127;
            g_W1T[(MAXR * DD + o) * KH + c] = __float2half_rn(root[c * DD + o]);
        } else {
            int t = idx - n1;
            int o = t >> 7, c = t & 127;   // o<128: w_root row o ; o>=128: w_rel row o-128
            float w = (o < DD) ? w_root[o * DD + c] : w_rel[(o - DD) * DD + c];
            g_W2T[o * KH + c] = __float2half_rn(w);
        }
    } else if (id < Z + W + n * 16) {
        int i = id - Z - W;
        int nn = i >> 4, g = i & 15;
        const float4* src = (const float4*)(x + (size_t)nn * DD + g * 8);
        *(uint4*)(g_A1 + (size_t)nn * KH + g * 8) = cvt8h(src[0], src[1]);
    }
}

// ---------------- branch-B zero: cnt + hist (owned by bucketing chain) ----------------
__global__ void k_zero_cnt_hist(int n, int r, int nb) {
    int i = blockIdx.x * blockDim.x + threadIdx.x;
    if (i < (n * r + 3) / 4) ((int4*)g_cnt)[i] = make_int4(0, 0, 0, 0);
    if (i < nb) g_hist[i] = 0;
}

// ---------------- per-(dst,rel) count + per-(srcblk,rel) histogram ----------------
__global__ void k_count_hist(const void* __restrict__ ei, const void* __restrict__ et, int e,
                             int r) {
    int i = blockIdx.x * blockDim.x + threadIdx.x;
    if (i >= e) return;
    int w64 = is_w64((const int*)ei);
    int src = (int)getIdx(ei, i, w64);
    int dst = (int)getIdx(ei, (size_t)e + i, w64);
    int t = (int)getIdx(et, i, w64);
    atomicAdd(&g_cnt[dst * r + t], 1);
    atomicAdd(&g_hist[(src >> 7) * r + t], 1);
}

// ---------------- exclusive scan over nb buckets (single block) ----------------
__global__ void s_scan(int nb) {
    __shared__ int part[1024];
    int chunk = (nb + 1023) / 1024;
    int beg = threadIdx.x * chunk;
    int end = min(beg + chunk, nb);
    int s = 0;
    for (int i = beg; i < end; i++) s += g_hist[i];
    part[threadIdx.x] = s;
    __syncthreads();
    for (int off = 1; off < 1024; off <<= 1) {
        int v = (threadIdx.x >= off) ? part[threadIdx.x - off] : 0;
        __syncthreads();
        part[threadIdx.x] += v;
        __syncthreads();
    }
    int run = (threadIdx.x == 0) ? 0 : part[threadIdx.x - 1];
    for (int i = beg; i < end; i++) {
        int h = g_hist[i];
        g_seg[i] = run;
        g_cur[i] = run;
        run += h;
    }
    if (threadIdx.x == 0) g_seg[nb] = part[1023];
}

// ---------------- place edges into buckets (one edge / thread — measured best) ----------------
__global__ void s_place(const void* __restrict__ ei, const void* __restrict__ et, int e, int r) {
    int i = blockIdx.x * blockDim.x + threadIdx.x;
    if (i >= e) return;
    int w64 = is_w64((const int*)ei);
    int src = (int)getIdx(ei, i, w64);
    int dst = (int)getIdx(ei, (size_t)e + i, w64);
    int t = (int)getIdx(et, i, w64);
    int pos = atomicAdd(&g_cur[(src >> 7) * r + t], 1);
    g_epk[pos] = (uint32_t)dst | ((uint32_t)(src & 127) << 17);
    int c = g_cnt[dst * r + t];
    g_enorm[pos] = 1.0f / (float)(c > 0 ? c : 1);
}

// ---------------- HMMA fp16 GEMM (K=128, double-buffered) with fused scatter ----------------
// MODE 0 (grid 1 x mtiles): g_A1 @ W1T root block -> g_yroot
// MODE 1 (grid 8 x mtiles): g_A1 @ W1T relation bx -> smem -> scatter into g_agg
// MODE 2 (grid 2 x mtiles): g_A2 @ g_W2T (d_out zeroed in prep)
//   bx 0 (w_root half): red.add (acc + bias) into Cext rows
//   bx 1 (w_rel half):  tile -> smem -> atomic scatter into Cext over edges
template <int MODE>
__global__ __launch_bounds__(256, 2) void k_gemm_mma(float* __restrict__ Cext,
                                                     const float* __restrict__ bias, int M,
                                                     int r) {
    const __half* A  = (MODE == 2) ? g_A2 : g_A1;
    const __half* Bw = (MODE == 2) ? g_W2T : g_W1T;
    const int nB0 = (MODE == 0) ? MAXR * DD : blockIdx.x * 128;

    extern __shared__ char dsm[];
    uint32_t s0 = smem_u32(dsm);   // [As0 16K][Bs0 16K][As1 16K][Bs1 16K]

    int tid = threadIdx.x;
    int wid = tid >> 5, lane = tid & 31;
    int wm = wid & 3, wn = wid >> 2;
    int m0 = blockIdx.y * 128;

    float acc[2][8][4];
#pragma unroll
    for (int i = 0; i < 2; i++)
#pragma unroll
        for (int j = 0; j < 8; j++)
#pragma unroll
            for (int q = 0; q < 4; q++) acc[i][j][q] = 0.f;

    auto load_tile = [&](int kt, int buf) {
        uint32_t sa = s0 + buf * 32768, sb = sa + 16384;
#pragma unroll
        for (int i = 0; i < 4; i++) {
            int id = i * 256 + tid;
            int row = id >> 3, c8 = id & 7;
            uint32_t soff = row * 128 + ((c8 ^ (row & 7)) * 16);
            const void* gA = A + (size_t)(m0 + row) * KH + kt * 64 + c8 * 8;
            int szA = (m0 + row < M) ? 16 : 0;
            asm volatile("cp.async.ca.shared.global [%0], [%1], 16, %2;" ::"r"(sa + soff),
                         "l"(gA), "r"(szA)
                         : "memory");
            const void* gB = Bw + (size_t)(nB0 + row) * KH + kt * 64 + c8 * 8;
            asm volatile("cp.async.ca.shared.global [%0], [%1], 16;" ::"r"(sb + soff), "l"(gB)
                         : "memory");
        }
        asm volatile("cp.async.commit_group;" ::: "memory");
    };

    uint32_t fa[2][2][4];
    uint32_t fb[2][8][2];

    auto ldsm_stage = [&](uint32_t sA, uint32_t sB, int k16, int st) {
#pragma unroll
        for (int mi = 0; mi < 2; mi++) {
            int row = wm * 32 + mi * 16 + (lane & 15);
            int g = k16 * 2 + (lane >> 4);
            uint32_t addr = sA + row * 128 + ((g ^ (row & 7)) * 16);
            asm volatile("ldmatrix.sync.aligned.m8n8.x4.shared.b16 {%0,%1,%2,%3}, [%4];"
                         : "=r"(fa[st][mi][0]), "=r"(fa[st][mi][1]), "=r"(fa[st][mi][2]),
                           "=r"(fa[st][mi][3])
                         : "r"(addr));
        }
#pragma unroll
        for (int nq = 0; nq < 4; nq++) {
            int row = wn * 64 + nq * 16 + (lane & 15);
            int g = k16 * 2 + (lane >> 4);
            uint32_t addr = sB + row * 128 + ((g ^ (row & 7)) * 16);
            uint32_t r0, r1, r2, r3;
            asm volatile("ldmatrix.sync.aligned.m8n8.x4.shared.b16 {%0,%1,%2,%3}, [%4];"
                         : "=r"(r0), "=r"(r1), "=r"(r2), "=r"(r3)
                         : "r"(addr));
            fb[st][nq * 2 + 0][0] = r0; fb[st][nq * 2 + 0][1] = r2;
            fb[st][nq * 2 + 1][0] = r1; fb[st][nq * 2 + 1][1] = r3;
        }
    };
    auto hmma_stage = [&](int st) {
#pragma unroll
        for (int mi = 0; mi < 2; mi++)
#pragma unroll
            for (int ni = 0; ni < 8; ni++)
                asm volatile(
                    "mma.sync.aligned.m16n8k16.row.col.f32.f16.f16.f32 "
                    "{%0,%1,%2,%3}, {%4,%5,%6,%7}, {%8,%9}, {%0,%1,%2,%3};"
                    : "+f"(acc[mi][ni][0]), "+f"(acc[mi][ni][1]), "+f"(acc[mi][ni][2]),
                      "+f"(acc[mi][ni][3])
                    : "r"(fa[st][mi][0]), "r"(fa[st][mi][1]), "r"(fa[st][mi][2]),
                      "r"(fa[st][mi][3]), "r"(fb[st][ni][0]), "r"(fb[st][ni][1]));
    };

    const int NK = KH / 64;   // 2
    load_tile(0, 0);
    int buf = 0;
    for (int kt = 0; kt < NK; kt++) {
        if (kt + 1 < NK)
            load_tile(kt + 1, buf ^ 1);
        else
            asm volatile("cp.async.commit_group;" ::: "memory");
        asm volatile("cp.async.wait_group 1;" ::: "memory");
        __syncthreads();

        uint32_t sA = s0 + buf * 32768, sB = sA + 16384;
        ldsm_stage(sA, sB, 0, 0);
#pragma unroll
        for (int k16 = 0; k16 < 4; k16++) {
            if (k16 < 3) ldsm_stage(sA, sB, k16 + 1, (k16 + 1) & 1);
            hmma_stage(k16 & 1);
        }
        __syncthreads();
        buf ^= 1;
    }

    if (MODE == 0) {
        // root block -> g_yroot (plain stores; g_yroot private to layer 1)
#pragma unroll
        for (int mi = 0; mi < 2; mi++) {
            int r0 = m0 + wm * 32 + mi * 16 + (lane >> 2);
#pragma unroll
            for (int ni = 0; ni < 8; ni++) {
                int ct = wn * 64 + ni * 8 + (lane & 3) * 2;
                if (r0 < M)
                    *(float2*)(g_yroot + (size_t)r0 * DD + ct) =
                        make_float2(acc[mi][ni][0], acc[mi][ni][1]);
                if (r0 + 8 < M)
                    *(float2*)(g_yroot + (size_t)(r0 + 8) * DD + ct) =
                        make_float2(acc[mi][ni][2], acc[mi][ni][3]);
            }
        }
    } else if (MODE == 2 && blockIdx.x == 0) {
        // w_root half: atomically add acc + bias into d_out (zeroed in prep)
#pragma unroll
        for (int mi = 0; mi < 2; mi++) {
            int r0 = m0 + wm * 32 + mi * 16 + (lane >> 2);
#pragma unroll
            for (int ni = 0; ni < 8; ni++) {
                int ct = wn * 64 + ni * 8 + (lane & 3) * 2;
                float b0 = bias[ct], b1 = bias[ct + 1];
                if (r0 < M) {
                    float* p = Cext + (size_t)r0 * DD + ct;
                    asm volatile("red.global.add.v2.f32 [%0], {%1,%2};" ::"l"(p),
                                 "f"(acc[mi][ni][0] + b0), "f"(acc[mi][ni][1] + b1)
                                 : "memory");
                }
                if (r0 + 8 < M) {
                    float* p = Cext + (size_t)(r0 + 8) * DD + ct;
                    asm volatile("red.global.add.v2.f32 [%0], {%1,%2};" ::"l"(p),
                                 "f"(acc[mi][ni][2] + b0), "f"(acc[mi][ni][3] + b1)
                                 : "memory");
                }
            }
        }
    } else {
        // scatter epilogue: tile -> smem, walk edge bucket, atomic-add rows (pipelined)
        float* ts = (float*)dsm;   // [128][132]
#pragma unroll
        for (int mi = 0; mi < 2; mi++) {
            int r0 = wm * 32 + mi * 16 + (lane >> 2);
#pragma unroll
            for (int ni = 0; ni < 8; ni++) {
                int ct = wn * 64 + ni * 8 + (lane & 3) * 2;
                *(float2*)&ts[r0 * 132 + ct] = make_float2(acc[mi][ni][0], acc[mi][ni][1]);
                *(float2*)&ts[(r0 + 8) * 132 + ct] =
                    make_float2(acc[mi][ni][2], acc[mi][ni][3]);
            }
        }
        __syncthreads();
        int s, eN;
        if (MODE == 1) {
            int key = blockIdx.y * r + blockIdx.x;
            s = g_seg[key];
            eN = g_seg[key + 1];
        } else {
            s = g_seg[blockIdx.y * r];
            eN = g_seg[blockIdx.y * r + r];
        }
        float* target = (MODE == 1) ? g_agg : Cext;
        int ie = s + wid;
        uint32_t pk = 0;
        float nm = 1.0f;
        if (ie < eN) {
            pk = g_epk[ie];
            if (MODE == 1) nm = g_enorm[ie];
        }
        while (ie < eN) {
            int nxt = ie + 8;
            uint32_t pk2 = 0;
            float nm2 = 1.0f;
            if (nxt < eN) {
                pk2 = g_epk[nxt];
                if (MODE == 1) nm2 = g_enorm[nxt];
            }
            int dst = pk & 0x1FFFF, sl = pk >> 17;
            float4 v = *(float4*)&ts[sl * 132 + lane * 4];
            float* p = target + (size_t)dst * DD + lane * 4;
            asm volatile("red.global.add.v4.f32 [%0], {%1,%2,%3,%4};" ::"l"(p), "f"(v.x * nm),
                         "f"(v.y * nm), "f"(v.z * nm), "f"(v.w * nm)
                         : "memory");
            pk = pk2;
            nm = nm2;
            ie = nxt;
        }
    }
}

// ---------------- compose h1 = agg + yroot + bias1 -> fp16 into A2 ----------------
__global__ void k_compose(const float* __restrict__ bias1, int n) {
    int i = blockIdx.x * blockDim.x + threadIdx.x;
    if (i >= n * 16) return;
    int nn = i >> 4, g = i & 15;
    const float4* pa = (const float4*)(g_agg + (size_t)nn * DD + g * 8);
    const float4* py = (const float4*)(g_yroot + (size_t)nn * DD + g * 8);
    const float4* pb = (const float4*)(bias1 + g * 8);
    float4 a0 = pa[0], a1 = pa[1], y0 = py[0], y1 = py[1], b0 = pb[0], b1 = pb[1];
    float4 h0 = make_float4(a0.x + y0.x + b0.x, a0.y + y0.y + b0.y, a0.z + y0.z + b0.z,
                            a0.w + y0.w + b0.w);
    float4 h1 = make_float4(a1.x + y1.x + b1.x, a1.y + y1.y + b1.y, a1.z + y1.z + b1.z,
                            a1.w + y1.w + b1.w);
    *(uint4*)(g_A2 + (size_t)nn * KH + g * 8) = cvt8h(h0, h1);
}

extern "C" void kernel_launch(void* const* d_in, const int* in_sizes, int n_in,
                              void* d_out, int out_size) {
    const float* x      = (const float*)d_in[0];
    const void*  ei     = d_in[1];
    const void*  et     = d_in[2];
    const float* basis  = (const float*)d_in[3];
    const float* comp   = (const float*)d_in[4];
    const float* root   = (const float*)d_in[5];
    const float* bias1  = (const float*)d_in[6];
    const float* w_rel  = (const float*)d_in[7];
    const float* b_rel  = (const float*)d_in[8];
    const float* w_root = (const float*)d_in[9];

    int n = in_sizes[0] / DD;
    int e = in_sizes[2];
    int b = in_sizes[3] / (DD * DD);
    int r = in_sizes[4] / b;   // 8

    int mtiles = (n + 127) / 128;
    int nb = mtiles * r;
    const int SMEM = 69632;
    cudaFuncSetAttribute(k_gemm_mma<0>, cudaFuncAttributeMaxDynamicSharedMemorySize, SMEM);
    cudaFuncSetAttribute(k_gemm_mma<1>, cudaFuncAttributeMaxDynamicSharedMemorySize, SMEM);
    cudaFuncSetAttribute(k_gemm_mma<2>, cudaFuncAttributeMaxDynamicSharedMemorySize, SMEM);

    // Lazily-created side stream + events (host-side objects only; identical
    // GPU work / graph topology on every call).
    static cudaStream_t s2 = nullptr;
    static cudaEvent_t evFork = nullptr, evJoin = nullptr;
    if (!s2) {
        cudaStreamCreateWithFlags(&s2, cudaStreamNonBlocking);
        cudaEventCreateWithFlags(&evFork, cudaEventDisableTiming);
        cudaEventCreateWithFlags(&evJoin, cudaEventDisableTiming);
    }
    bool fork = (s2 != nullptr && evFork != nullptr && evJoin != nullptr);
    cudaStream_t sb = fork ? s2 : (cudaStream_t)0;

    // Branch A (stream 0): prep -> root GEMM (no edge dependency)
    // Branch B (side):     zero cnt/hist -> count -> scan -> place
    if (fork) {
        cudaEventRecord(evFork, 0);
        cudaStreamWaitEvent(s2, evFork, 0);
    }
    k_zero_cnt_hist<<<((n * r + 3) / 4 + 255) / 256, 256, 0, sb>>>(n, r, nb);
    {
        int total = n * 32 + (NOUT1 + 256) * DD + n * 16;
        k_prep<<<(total + 255) / 256, 256>>>(x, basis, comp, root, w_rel, w_root,
                                             (float*)d_out, n, b);
    }
    k_count_hist<<<(e + 255) / 256, 256, 0, sb>>>(ei, et, e, r);
    k_gemm_mma<0><<<dim3(1, mtiles), 256, SMEM>>>(nullptr, nullptr, n, r);   // branch A
    s_scan<<<1, 1024, 0, sb>>>(nb);
    s_place<<<(e + 255) / 256, 256, 0, sb>>>(ei, et, e, r);
    if (fork) {
        cudaEventRecord(evJoin, s2);
        cudaStreamWaitEvent((cudaStream_t)0, evJoin, 0);
    }

    // relations GEMM (K=128 fp16)
    k_gemm_mma<1><<<dim3(MAXR, mtiles), 256, SMEM>>>(nullptr, nullptr, n, r);

    // compose h1
    k_compose<<<(n * 16 + 255) / 256, 256>>>(bias1, n);

    // layer-2 both halves in one launch (all-atomic into zeroed d_out)
    k_gemm_mma<2><<<dim3(2, mtiles), 256, SMEM>>>((float*)d_out, b_rel, n, r);
}